// round 4
// baseline (speedup 1.0000x reference)
#include <cuda_runtime.h>
#include <math.h>
#include <stdint.h>

// ---------------- problem constants ----------------
#define B_ 256
#define S_ 14
#define C_ 2513
#define SB 3584          // S_*B_
#define BH 262144        // B_*H_
#define G4 4096          // 4*H_

// ---------------- mma.sync GEMM config ----------------
#define ASTRIDE 36                     // padded SMEM row stride (floats)
#define STAGEF  (128 * ASTRIDE)        // floats per operand per stage = 4608
#define SMEM_FLOATS (4 * STAGEF + 128) // 2 stages x (A+B) + bias row
#define SMEM_BYTES  (SMEM_FLOATS * 4)  // 74240

// ---------------- scratch (device globals) ----------------
__device__ float g_xT  [SB * 1024];          // tf32-rounded, [S,B,F]
__device__ float g_xg_r[(size_t)SB * G4];    // gate-interleaved [m][u*4+g]
__device__ float g_xg_u[(size_t)SB * G4];
__device__ float g_hs  [SB * 1024];
__device__ float g_cs  [SB * 1024];
__device__ float g_hu  [2 * SB * 1024];      // tf32-rounded ping-pong
__device__ float g_cu  [SB * 1024];
__device__ float g_hn  [SB * 1024];          // tf32-rounded final hiddens
// pre-rounded (+gate-permuted) weight copies
__device__ float g_wihr[(size_t)G4 * 1024];
__device__ float g_wihu[(size_t)G4 * 1024];
__device__ float g_whhu[(size_t)G4 * 1024];
__device__ float g_wc  [(size_t)C_ * 1024];

__device__ __forceinline__ float sigf(float x) { return 1.0f / (1.0f + expf(-x)); }

// ---------------- low-level helpers ----------------
__device__ __forceinline__ uint32_t f2tf(float x) {
    uint32_t r; asm("cvt.rna.tf32.f32 %0, %1;" : "=r"(r) : "f"(x)); return r;
}
__device__ __forceinline__ float roundtf(float x) { return __uint_as_float(f2tf(x)); }
__device__ __forceinline__ uint32_t smaddr(const void* p) {
    uint32_t a;
    asm("{ .reg .u64 t; cvta.to.shared.u64 t, %1; cvt.u32.u64 %0, t; }" : "=r"(a) : "l"(p));
    return a;
}
__device__ __forceinline__ void cp16(uint32_t d, const void* s) {
    asm volatile("cp.async.cg.shared.global [%0], [%1], 16;" :: "r"(d), "l"(s));
}
__device__ __forceinline__ void cp16z(uint32_t d, const void* s, int sz) {
    asm volatile("cp.async.cg.shared.global [%0], [%1], 16, %2;" :: "r"(d), "l"(s), "r"(sz));
}
__device__ __forceinline__ void cpcommit() { asm volatile("cp.async.commit_group;"); }
__device__ __forceinline__ void cpwait0()  { asm volatile("cp.async.wait_group 0;"); }
__device__ __forceinline__ void cpwait1()  { asm volatile("cp.async.wait_group 1;"); }

__device__ __forceinline__ void mma8(float* d, const uint32_t* a, const uint32_t* b) {
    asm volatile(
        "mma.sync.aligned.m16n8k8.row.col.f32.tf32.tf32.f32 "
        "{%0,%1,%2,%3},{%4,%5,%6,%7},{%8,%9},{%0,%1,%2,%3};"
        : "+f"(d[0]), "+f"(d[1]), "+f"(d[2]), "+f"(d[3])
        : "r"(a[0]), "r"(a[1]), "r"(a[2]), "r"(a[3]), "r"(b[0]), "r"(b[1]));
}

// ---------------- stage issue: global -> SMEM via cp.async ----------------
// Weights are pre-permuted, so B row index is n0+row directly.
// EDGE: zero-fill rows with n0+row >= Nb (classifier N-edge only).
template <int EDGE>
__device__ __forceinline__ void stage_issue(
    float* sm, int s, const float* __restrict__ A, const float* __restrict__ W,
    int m0, int n0, int kt, int Nb, int tid)
{
    float* dA = sm + s * 2 * STAGEF;
    float* dB = dA + STAGEF;
    const float* Ap = A + (size_t)m0 * 1024 + kt * 32;
    const float* Wp = W + (size_t)n0 * 1024 + kt * 32;
#pragma unroll
    for (int i = 0; i < 4; i++) {
        int idx = tid + (i << 8);
        int row = idx >> 3, c4 = idx & 7;
        cp16(smaddr(dA + row * ASTRIDE + c4 * 4), Ap + (size_t)row * 1024 + c4 * 4);
        if (EDGE) {
            int ok = (n0 + row < Nb);
            cp16z(smaddr(dB + row * ASTRIDE + c4 * 4),
                  Wp + (size_t)(ok ? row : 0) * 1024 + c4 * 4, ok ? 16 : 0);
        } else {
            cp16(smaddr(dB + row * ASTRIDE + c4 * 4), Wp + (size_t)row * 1024 + c4 * 4);
        }
    }
    cpcommit();
}

// ---------------- stage compute ----------------
// Logical-k permutation: MMA instance j, fragment slot (tig,pos) consumes phys
// column tig*8 + 2*j + pos (same map for A and B => GEMM invariant). Each lane's
// fragments for all 4 instances come from 2 contiguous float4 per row.
// Operands are pre-rounded to tf32, so bits load directly (no cvt).
__device__ __forceinline__ void stage_compute(
    const float* sm, int s, int wm, int wn, int g, int tig, float acc[4][4][4])
{
    const float* bA = sm + s * 2 * STAGEF + (size_t)(wm * 64 + g) * ASTRIDE + tig * 8;
    const float* bB = sm + s * 2 * STAGEF + STAGEF + (size_t)(wn * 32 + g) * ASTRIDE + tig * 8;
#pragma unroll
    for (int h = 0; h < 2; h++) {
        uint4 bq[4];
#pragma unroll
        for (int ni = 0; ni < 4; ni++)
            bq[ni] = *(const uint4*)(bB + ni * 8 * ASTRIDE + h * 4);
#pragma unroll
        for (int mi = 0; mi < 4; mi++) {
            uint4 alo = *(const uint4*)(bA + mi * 16 * ASTRIDE + h * 4);
            uint4 ahi = *(const uint4*)(bA + (mi * 16 + 8) * ASTRIDE + h * 4);
            uint32_t af0[4] = {alo.x, ahi.x, alo.y, ahi.y};
            uint32_t af1[4] = {alo.z, ahi.z, alo.w, ahi.w};
#pragma unroll
            for (int ni = 0; ni < 4; ni++) {
                uint32_t bf0[2] = {bq[ni].x, bq[ni].y};
                uint32_t bf1[2] = {bq[ni].z, bq[ni].w};
                mma8(acc[mi][ni], af0, bf0);
                mma8(acc[mi][ni], af1, bf1);
            }
        }
    }
}

// ---------------- full K=1024 mainloop (2-stage pipeline) ----------------
template <int EDGE>
__device__ __forceinline__ void run_mainloop(
    float* sm, const float* __restrict__ A, const float* __restrict__ W,
    int m0, int n0, int Nb, float acc[4][4][4],
    int tid, int wm, int wn, int g, int tig)
{
    stage_issue<EDGE>(sm, 0, A, W, m0, n0, 0, Nb, tid);
    stage_issue<EDGE>(sm, 1, A, W, m0, n0, 1, Nb, tid);
#pragma unroll 1
    for (int kt = 0; kt < 32; kt++) {
        int s = kt & 1;
        if (kt + 1 < 32) cpwait1(); else cpwait0();
        __syncthreads();
        stage_compute(sm, s, wm, wn, g, tig, acc);
        __syncthreads();
        if (kt + 2 < 32) stage_issue<EDGE>(sm, s, A, W, m0, n0, kt + 2, Nb, tid);
    }
}

// ---------------- fused tensor-core LSTM step ----------------
__global__ void __launch_bounds__(256) k_mma_lstm(
    const float* __restrict__ Hin, const float* __restrict__ Whh,
    const float* __restrict__ xg, const float* __restrict__ Cin,
    float* __restrict__ Hout, float* __restrict__ Cout,
    float* __restrict__ Hfin, int final_t)
{
    extern __shared__ float sm[];
    const int tid = threadIdx.x, lane = tid & 31, wid = tid >> 5;
    const int wm = wid & 1, wn = wid >> 1, g = lane >> 2, tig = lane & 3;
    const int m0 = blockIdx.y * 128, n0 = blockIdx.x * 128;

    float acc[4][4][4];
#pragma unroll
    for (int a = 0; a < 4; a++)
#pragma unroll
        for (int b = 0; b < 4; b++)
#pragma unroll
            for (int c = 0; c < 4; c++) acc[a][b][c] = 0.f;

    run_mainloop<0>(sm, Hin, Whh, m0, n0, 0x7fffffff, acc, tid, wm, wn, g, tig);

#pragma unroll
    for (int mi = 0; mi < 4; mi++) {
        const int R0 = m0 + wm * 64 + mi * 16;
#pragma unroll
        for (int ni = 0; ni < 4; ni++) {
            const int V0 = n0 + wn * 32 + ni * 8;
            float c0 = acc[mi][ni][0], c1 = acc[mi][ni][1];
            float c2 = acc[mi][ni][2], c3 = acc[mi][ni][3];
            int p = tig & 1;
            float x = p ? c0 : c2, y = p ? c1 : c3;
            float sx = __shfl_xor_sync(0xffffffffu, x, 1);
            float sy = __shfl_xor_sync(0xffffffffu, y, 1);
            float pi, pf, pg, po; int row;
            if (!p) { pi = c0; pf = c1; pg = sx; po = sy; row = R0 + g; }
            else    { pi = sx; pf = sy; pg = c2; po = c3; row = R0 + g + 8; }
            int u = (V0 >> 2) + (tig >> 1);
            float4 xv = *(const float4*)(xg + (size_t)row * G4 + u * 4);
            float ci = Cin[(size_t)row * 1024 + u];
            float cn = sigf(pf + xv.y) * ci + sigf(pi + xv.x) * tanhf(pg + xv.z);
            float hv = sigf(po + xv.w) * tanhf(cn);
            float hr = roundtf(hv);                 // pre-round for next GEMM
            Hout[(size_t)row * 1024 + u] = hr;
            Cout[(size_t)row * 1024 + u] = cn;
            if ((row >> 8) == final_t) Hfin[(size_t)row * 1024 + u] = hr;
        }
    }
}

// ---------------- tensor-core linear ----------------
// MODE 1: projection -> gate-interleaved output, bias b0[wr]+b1[wr] (remapped)
// MODE 0: classifier -> rows permuted (b*S+s), N-edge predicated, bias b0[n]
template <int MODE>
__global__ void __launch_bounds__(256) k_mma_lin(
    const float* __restrict__ A, const float* __restrict__ W,
    float* __restrict__ Out, const float* __restrict__ b0,
    const float* __restrict__ b1, int N)
{
    extern __shared__ float sm[];
    float* biasS = sm + 4 * STAGEF;
    const int tid = threadIdx.x, lane = tid & 31, wid = tid >> 5;
    const int wm = wid & 1, wn = wid >> 1, g = lane >> 2, tig = lane & 3;
    const int m0 = blockIdx.y * 128, n0 = blockIdx.x * 128;

    if (tid < 128) {
        int np = n0 + tid;
        float bv = 0.f;
        if (MODE == 1) { int wr = ((np & 3) << 10) | (np >> 2); bv = b0[wr] + b1[wr]; }
        else if (np < N) bv = b0[np];
        biasS[tid] = bv;
    }

    float acc[4][4][4];
#pragma unroll
    for (int a = 0; a < 4; a++)
#pragma unroll
        for (int b = 0; b < 4; b++)
#pragma unroll
            for (int c = 0; c < 4; c++) acc[a][b][c] = 0.f;

    run_mainloop<(MODE == 0) ? 1 : 0>(sm, A, W, m0, n0, MODE ? 0x7fffffff : N,
                                      acc, tid, wm, wn, g, tig);

#pragma unroll
    for (int mi = 0; mi < 4; mi++) {
        const int R0 = m0 + wm * 64 + mi * 16;
#pragma unroll
        for (int ni = 0; ni < 4; ni++) {
            const int V0 = n0 + wn * 32 + ni * 8;
            const int v = V0 + 2 * tig;
            const float bA0 = biasS[v - n0], bA1 = biasS[v - n0 + 1];
            const int r1 = R0 + g, r2 = R0 + g + 8;
            if (MODE == 1) {
                float2 s1 = make_float2(acc[mi][ni][0] + bA0, acc[mi][ni][1] + bA1);
                float2 s2 = make_float2(acc[mi][ni][2] + bA0, acc[mi][ni][3] + bA1);
                *(float2*)(Out + (size_t)r1 * G4 + v) = s1;
                *(float2*)(Out + (size_t)r2 * G4 + v) = s2;
            } else {
                int or1 = (r1 & 255) * S_ + (r1 >> 8);
                int or2 = (r2 & 255) * S_ + (r2 >> 8);
                if (v < N) {
                    Out[(size_t)or1 * N + v] = acc[mi][ni][0] + bA0;
                    Out[(size_t)or2 * N + v] = acc[mi][ni][2] + bA0;
                }
                if (v + 1 < N) {
                    Out[(size_t)or1 * N + v + 1] = acc[mi][ni][1] + bA1;
                    Out[(size_t)or2 * N + v + 1] = acc[mi][ni][3] + bA1;
                }
            }
        }
    }
}

// ---------------- prep kernels ----------------
// transpose [B,S,F] -> [S,B,F], rounded to tf32
__global__ void k_transpose(const float4* __restrict__ in, float4* __restrict__ out) {
    const int F4 = 1024 / 4;
    int idx = blockIdx.x * blockDim.x + threadIdx.x;
    if (idx >= SB * F4) return;
    int f4  = idx % F4;
    int row = idx / F4;
    int b = row % B_;
    int s = row / B_;
    float4 v = in[(size_t)(b * S_ + s) * F4 + f4];
    v.x = roundtf(v.x); v.y = roundtf(v.y); v.z = roundtf(v.z); v.w = roundtf(v.w);
    out[idx] = v;
}

// weight prep: out[np][k] = round(in[wr(np)][k]); REMAP = gate interleave
template <int REMAP>
__global__ void k_prep_w(const float4* __restrict__ in, float4* __restrict__ out, int rows) {
    int idx = blockIdx.x * blockDim.x + threadIdx.x;
    if (idx >= rows * 256) return;
    int row = idx >> 8, c = idx & 255;
    int wr = REMAP ? (((row & 3) << 10) | (row >> 2)) : row;
    float4 v = in[(size_t)wr * 256 + c];
    v.x = roundtf(v.x); v.y = roundtf(v.y); v.z = roundtf(v.z); v.w = roundtf(v.w);
    out[(size_t)row * 256 + c] = v;
}

// rounded copy (hs -> hu0)
__global__ void k_roundcopy(const float4* __restrict__ in, float4* __restrict__ out, int n4) {
    int i = blockIdx.x * blockDim.x + threadIdx.x;
    if (i >= n4) return;
    float4 v = in[i];
    v.x = roundtf(v.x); v.y = roundtf(v.y); v.z = roundtf(v.z); v.w = roundtf(v.w);
    out[i] = v;
}

// ---------------- FFMA rolling LSTM step (M=256, latency-bound) ----------------
__global__ void __launch_bounds__(256) k_lstm_step(
    const float* __restrict__ Hin, const float* __restrict__ Whh,
    const float* __restrict__ xg, const float* __restrict__ Cin,
    float* __restrict__ Hout, float* __restrict__ Cout, int zeroInit)
{
    constexpr int BM = 64, TM = 4;
    __shared__ float As[16][BM + 4];
    __shared__ float Ws[16][132];
    const int tid = threadIdx.x;
    const int tx = tid & 15, ty = tid >> 4;
    const int m0 = blockIdx.y * BM;
    const int n0 = blockIdx.x * 128;

    float acc[TM][8];
#pragma unroll
    for (int i = 0; i < TM; i++)
#pragma unroll
        for (int j = 0; j < 8; j++) acc[i][j] = 0.f;

    if (!zeroInit) {
        const int lr = tid >> 2;
        const int lk = (tid & 3) << 2;
        for (int kt = 0; kt < 1024; kt += 16) {
            {
                int row = lr;
                float4 v = *(const float4*)&Hin[(size_t)(m0 + row) * 1024 + kt + lk];
                As[lk + 0][row] = v.x; As[lk + 1][row] = v.y;
                As[lk + 2][row] = v.z; As[lk + 3][row] = v.w;
            }
#pragma unroll
            for (int r = 0; r < 2; r++) {
                int wr = lr + r * 64;
                int np = n0 + wr;
                int wrow = ((np & 3) << 10) + (np >> 2);
                float4 v = *(const float4*)&Whh[(size_t)wrow * 1024 + kt + lk];
                Ws[lk + 0][wr] = v.x; Ws[lk + 1][wr] = v.y;
                Ws[lk + 2][wr] = v.z; Ws[lk + 3][wr] = v.w;
            }
            __syncthreads();
#pragma unroll
            for (int k = 0; k < 16; k++) {
                float a[TM], w[8];
#pragma unroll
                for (int i = 0; i < TM; i++) a[i] = As[k][ty * TM + i];
#pragma unroll
                for (int j = 0; j < 8; j++) w[j] = Ws[k][tx * 8 + j];
#pragma unroll
                for (int i = 0; i < TM; i++)
#pragma unroll
                    for (int j = 0; j < 8; j++) acc[i][j] = fmaf(a[i], w[j], acc[i][j]);
            }
            __syncthreads();
        }
    }

    const int u0 = (n0 + tx * 8) >> 2;
#pragma unroll
    for (int i = 0; i < TM; i++) {
        int m = m0 + ty * TM + i;
        const float* xr = xg + (size_t)m * G4;
#pragma unroll
        for (int uu = 0; uu < 2; uu++) {
            int u = u0 + uu;
            float4 xv = *(const float4*)&xr[(size_t)u * 4];
            float pi = acc[i][uu * 4 + 0] + xv.x;
            float pf = acc[i][uu * 4 + 1] + xv.y;
            float pg = acc[i][uu * 4 + 2] + xv.z;
            float po = acc[i][uu * 4 + 3] + xv.w;
            float c  = zeroInit ? 0.f : Cin[(size_t)m * 1024 + u];
            float c2 = sigf(pf) * c + sigf(pi) * tanhf(pg);
            float h2 = sigf(po) * tanhf(c2);
            Hout[(size_t)m * 1024 + u] = h2;
            Cout[(size_t)m * 1024 + u] = c2;
        }
    }
}

// ---------------- host orchestration ----------------
extern "C" void kernel_launch(void* const* d_in, const int* in_sizes, int n_in,
                              void* d_out, int out_size) {
    (void)in_sizes; (void)n_in; (void)out_size;
    const float* inp   = (const float*)d_in[0];
    const float* Wih_r = (const float*)d_in[1];
    const float* Whh_r = (const float*)d_in[2];
    const float* bih_r = (const float*)d_in[3];
    const float* bhh_r = (const float*)d_in[4];
    const float* Wih_u = (const float*)d_in[5];
    const float* Whh_u = (const float*)d_in[6];
    const float* bih_u = (const float*)d_in[7];
    const float* bhh_u = (const float*)d_in[8];
    const float* Wc    = (const float*)d_in[9];
    const float* bc    = (const float*)d_in[10];
    float* out = (float*)d_out;

    float *xT, *xg_r, *xg_u, *hs, *cs, *hu, *cu, *hn, *wihr, *wihu, *whhu, *wc;
    cudaGetSymbolAddress((void**)&xT,   g_xT);
    cudaGetSymbolAddress((void**)&xg_r, g_xg_r);
    cudaGetSymbolAddress((void**)&xg_u, g_xg_u);
    cudaGetSymbolAddress((void**)&hs,   g_hs);
    cudaGetSymbolAddress((void**)&cs,   g_cs);
    cudaGetSymbolAddress((void**)&hu,   g_hu);
    cudaGetSymbolAddress((void**)&cu,   g_cu);
    cudaGetSymbolAddress((void**)&hn,   g_hn);
    cudaGetSymbolAddress((void**)&wihr, g_wihr);
    cudaGetSymbolAddress((void**)&wihu, g_wihu);
    cudaGetSymbolAddress((void**)&whhu, g_whhu);
    cudaGetSymbolAddress((void**)&wc,   g_wc);
    float* hu0 = hu;
    float* hu1 = hu + (size_t)SB * 1024;

    cudaFuncSetAttribute(k_mma_lstm,   cudaFuncAttributeMaxDynamicSharedMemorySize, SMEM_BYTES);
    cudaFuncSetAttribute(k_mma_lin<1>, cudaFuncAttributeMaxDynamicSharedMemorySize, SMEM_BYTES);
    cudaFuncSetAttribute(k_mma_lin<0>, cudaFuncAttributeMaxDynamicSharedMemorySize, SMEM_BYTES);

    // 0) prep: round (+permute) all GEMM operand tensors
    {
        int total = SB * (1024 / 4);
        k_transpose<<<(total + 255) / 256, 256>>>((const float4*)inp, (float4*)xT);
        k_prep_w<1><<<(G4 * 256 + 255) / 256, 256>>>((const float4*)Wih_r, (float4*)wihr, G4);
        k_prep_w<1><<<(G4 * 256 + 255) / 256, 256>>>((const float4*)Wih_u, (float4*)wihu, G4);
        k_prep_w<1><<<(G4 * 256 + 255) / 256, 256>>>((const float4*)Whh_u, (float4*)whhu, G4);
        k_prep_w<0><<<(C_ * 256 + 255) / 256, 256>>>((const float4*)Wc, (float4*)wc, C_);
    }

    // 1) input projections -> gate-interleaved xg
    {
        dim3 g(G4 / 128, SB / 128);
        k_mma_lin<1><<<g, 256, SMEM_BYTES>>>(xT, wihr, xg_r, bih_r, bhh_r, G4);
        k_mma_lin<1><<<g, 256, SMEM_BYTES>>>(xT, wihu, xg_u, bih_u, bhh_u, G4);
    }

    // 2) rolling LSTM: 14 sequential FFMA steps, M = 256 (fp32-exact)
    for (int t = 0; t < S_; t++) {
        dim3 g(G4 / 128, B_ / 64);
        const float* hin = (t == 0) ? nullptr : hs + (size_t)(t - 1) * BH;
        const float* cin = (t == 0) ? nullptr : cs + (size_t)(t - 1) * BH;
        k_lstm_step<<<g, 256>>>(hin, Whh_r,
                                xg_r + (size_t)t * B_ * G4, cin,
                                hs + (size_t)t * BH, cs + (size_t)t * BH,
                                (t == 0) ? 1 : 0);
    }

    // 3) init unroll state (h rounded to tf32; c exact)
    k_roundcopy<<<(SB * 256 + 255) / 256, 256>>>((const float4*)hs, (float4*)hu0, SB * 256);
    cudaMemcpyAsync(cu, cs, sizeof(float) * (size_t)SB * 1024, cudaMemcpyDeviceToDevice, 0);

    // 4) unrolling LSTM: 15 batched tensor-core steps over the active prefix
    for (int j = 0; j <= S_; j++) {
        int nact = (15 - j < 14) ? (15 - j) : 14;
        const float* hin = (j & 1) ? hu1 : hu0;
        float*       ho  = (j & 1) ? hu0 : hu1;
        int final_t = S_ - j;
        dim3 g(G4 / 128, nact * 2);
        k_mma_lstm<<<g, 256, SMEM_BYTES>>>(hin, whhu, xg_u, cu, ho, cu, hn, final_t);
    }

    // 5) classifier (rows permuted to [B,S], N-edge)
    {
        dim3 g((C_ + 127) / 128, SB / 128);
        k_mma_lin<0><<<g, 256, SMEM_BYTES>>>(hn, wc, out, bc, nullptr, C_);
    }
}

// round 5
// speedup vs baseline: 1.3666x; 1.3666x over previous
#include <cuda_runtime.h>
#include <cuda_fp16.h>
#include <math.h>
#include <stdint.h>

// ---------------- problem constants ----------------
#define B_ 256
#define S_ 14
#define C_ 2513
#define SB 3584          // S_*B_
#define BH 262144        // B_*H_
#define G4 4096          // 4*H_

// ---------------- fp16 mma GEMM config ----------------
// 128x128 CTA tile, 8 warps (2x4), 64x32 warp tile, K-chunk 32, 4-stage cp.async.
#define STAGE_H   4096                  // halves per operand per stage (128*32)
#define SLOT_H    (2 * STAGE_H)         // A+B per stage = 8192 halves (16KB)
#define NSTAGE    4
#define HTILE_OFF (NSTAGE * SLOT_H)     // 32768 halves = 65536 B
#define SMEM_LSTM ((HTILE_OFF + 128 * 32) * 2)  // + h-tile 8KB = 73728 B
#define SMEM_LIN  (HTILE_OFF * 2 + 512)         // + bias row   = 66048 B

// ---------------- scratch (device globals) ----------------
__device__ __half g_xT [SB * 1024];            // fp16, k-permuted, [S,B,F]
__device__ float  g_xg_r[(size_t)SB * G4];     // fp32, gate-interleaved [m][u*4+g]
__device__ float  g_xg_u[(size_t)SB * G4];
__device__ float  g_hs [SB * 1024];            // rolling h (fp32, logical)
__device__ float  g_cs [SB * 1024];
__device__ __half g_hu [2 * SB * 1024];        // unroll h ping-pong (fp16, permuted)
__device__ float  g_cu [SB * 1024];
__device__ __half g_hn [SB * 1024];            // final hiddens (fp16, permuted)
__device__ __half g_wihr[(size_t)G4 * 1024];   // prepped weights (fp16, permuted)
__device__ __half g_wihu[(size_t)G4 * 1024];
__device__ __half g_whhu[(size_t)G4 * 1024];
__device__ __half g_wc [(size_t)C_ * 1024];

__device__ __forceinline__ float sigf(float x) { return 1.0f / (1.0f + expf(-x)); }

// logical-k permutation within each 32-k block (fragment-contiguity map)
__device__ __forceinline__ int perm_l(int p) {   // phys -> logical
    int b = (p >> 2) & 1, t = p >> 3, j = p & 3;
    return b * 16 + ((j < 2) ? (2 * t + j) : (2 * t + 8 + (j - 2)));
}
__device__ __forceinline__ int inv_l(int l) {    // logical -> phys
    int b = l >> 4, r = l & 15, hi = r >> 3, t = (r >> 1) & 3, e = r & 1;
    return t * 8 + b * 4 + hi * 2 + e;
}

// ---------------- low-level helpers ----------------
__device__ __forceinline__ uint32_t smaddr(const void* p) {
    uint32_t a;
    asm("{ .reg .u64 t; cvta.to.shared.u64 t, %1; cvt.u32.u64 %0, t; }" : "=r"(a) : "l"(p));
    return a;
}
__device__ __forceinline__ void cp16(uint32_t d, const void* s) {
    asm volatile("cp.async.cg.shared.global [%0], [%1], 16;" :: "r"(d), "l"(s));
}
__device__ __forceinline__ void cp16z(uint32_t d, const void* s, int sz) {
    asm volatile("cp.async.cg.shared.global [%0], [%1], 16, %2;" :: "r"(d), "l"(s), "r"(sz));
}
__device__ __forceinline__ void cpcommit() { asm volatile("cp.async.commit_group;"); }
template <int N>
__device__ __forceinline__ void cpwait() { asm volatile("cp.async.wait_group %0;" :: "n"(N)); }

__device__ __forceinline__ void mma16(float* d, const uint32_t* a, const uint32_t* b) {
    asm volatile(
        "mma.sync.aligned.m16n8k16.row.col.f32.f16.f16.f32 "
        "{%0,%1,%2,%3},{%4,%5,%6,%7},{%8,%9},{%0,%1,%2,%3};"
        : "+f"(d[0]), "+f"(d[1]), "+f"(d[2]), "+f"(d[3])
        : "r"(a[0]), "r"(a[1]), "r"(a[2]), "r"(a[3]), "r"(b[0]), "r"(b[1]));
}

// ---------------- stage issue: global -> SMEM via cp.async ----------------
template <int EDGE>
__device__ __forceinline__ void stage_issue(
    __half* sm, int slot, const __half* __restrict__ A, const __half* __restrict__ W,
    int m0, int n0, int kt, int Nb, int tid)
{
    __half* dA = sm + slot * SLOT_H;
    __half* dB = dA + STAGE_H;
    const __half* Ap = A + (size_t)m0 * 1024 + kt * 32;
    const __half* Wp = W + (size_t)n0 * 1024 + kt * 32;
#pragma unroll
    for (int i = 0; i < 2; i++) {
        int c = tid + (i << 8);
        int row = c >> 2, c16 = c & 3;
        cp16(smaddr(dA + row * 32 + c16 * 8), Ap + (size_t)row * 1024 + c16 * 8);
        if (EDGE) {
            int ok = (n0 + row < Nb);
            cp16z(smaddr(dB + row * 32 + c16 * 8),
                  Wp + (size_t)(ok ? row : 0) * 1024 + c16 * 8, ok ? 16 : 0);
        } else {
            cp16(smaddr(dB + row * 32 + c16 * 8), Wp + (size_t)row * 1024 + c16 * 8);
        }
    }
    cpcommit();
}

// ---------------- stage compute: one 32-k chunk, 32 MMAs/warp ----------------
__device__ __forceinline__ void stage_compute(
    const __half* sm, int slot, int wm, int wn, int g, int tig, float acc[4][4][4])
{
    const __half* bA = sm + slot * SLOT_H + (size_t)(wm * 64 + g) * 32 + tig * 8;
    const __half* bB = sm + slot * SLOT_H + STAGE_H + (size_t)(wn * 32 + g) * 32 + tig * 8;
    uint4 bq[4];
#pragma unroll
    for (int ni = 0; ni < 4; ni++)
        bq[ni] = *(const uint4*)(bB + ni * 8 * 32);
#pragma unroll
    for (int mi = 0; mi < 4; mi++) {
        uint4 alo = *(const uint4*)(bA + mi * 16 * 32);
        uint4 ahi = *(const uint4*)(bA + (mi * 16 + 8) * 32);
        uint32_t af0[4] = {alo.x, ahi.x, alo.y, ahi.y};
        uint32_t af1[4] = {alo.z, ahi.z, alo.w, ahi.w};
#pragma unroll
        for (int ni = 0; ni < 4; ni++) {
            uint32_t bf0[2] = {bq[ni].x, bq[ni].y};
            uint32_t bf1[2] = {bq[ni].z, bq[ni].w};
            mma16(acc[mi][ni], af0, bf0);
            mma16(acc[mi][ni], af1, bf1);
        }
    }
}

// ---------------- full K=1024 mainloop (4-stage, 1 sync/iter) ----------------
template <int EDGE>
__device__ __forceinline__ void run_mainloop(
    __half* sm, const __half* __restrict__ A, const __half* __restrict__ W,
    int m0, int n0, int Nb, float acc[4][4][4],
    int tid, int wm, int wn, int g, int tig)
{
    stage_issue<EDGE>(sm, 0, A, W, m0, n0, 0, Nb, tid);
    stage_issue<EDGE>(sm, 1, A, W, m0, n0, 1, Nb, tid);
    stage_issue<EDGE>(sm, 2, A, W, m0, n0, 2, Nb, tid);
#pragma unroll 1
    for (int kt = 0; kt < 32; kt++) {
        int slot = kt & 3;
        if (kt < 30)       cpwait<2>();
        else if (kt == 30) cpwait<1>();
        else               cpwait<0>();
        __syncthreads();
        if (kt + 3 < 32) stage_issue<EDGE>(sm, (kt + 3) & 3, A, W, m0, n0, kt + 3, Nb, tid);
        stage_compute(sm, slot, wm, wn, g, tig, acc);
    }
}

// ---------------- fused tensor-core LSTM step ----------------
__global__ void __launch_bounds__(256) k_mma_lstm(
    const __half* __restrict__ Hin, const __half* __restrict__ Whh,
    const float* __restrict__ xg, const float* __restrict__ Cin,
    __half* __restrict__ Hout, float* __restrict__ Cout,
    __half* __restrict__ Hfin, int final_t)
{
    extern __shared__ __half sm[];
    __half* hsm = sm + HTILE_OFF;
    const int tid = threadIdx.x, lane = tid & 31, wid = tid >> 5;
    const int wm = wid & 1, wn = wid >> 1, g = lane >> 2, tig = lane & 3;
    const int m0 = blockIdx.y * 128, n0 = blockIdx.x * 128;

    float acc[4][4][4];
#pragma unroll
    for (int a = 0; a < 4; a++)
#pragma unroll
        for (int b = 0; b < 4; b++)
#pragma unroll
            for (int c = 0; c < 4; c++) acc[a][b][c] = 0.f;

    run_mainloop<0>(sm, Hin, Whh, m0, n0, 0x7fffffff, acc, tid, wm, wn, g, tig);

#pragma unroll
    for (int mi = 0; mi < 4; mi++) {
        const int R0 = m0 + wm * 64 + mi * 16;
#pragma unroll
        for (int ni = 0; ni < 4; ni++) {
            const int V0 = n0 + wn * 32 + ni * 8;
            float c0 = acc[mi][ni][0], c1 = acc[mi][ni][1];
            float c2 = acc[mi][ni][2], c3 = acc[mi][ni][3];
            int p = tig & 1;
            float x = p ? c0 : c2, y = p ? c1 : c3;
            float sx = __shfl_xor_sync(0xffffffffu, x, 1);
            float sy = __shfl_xor_sync(0xffffffffu, y, 1);
            float pi, pf, pg, po; int row;
            if (!p) { pi = c0; pf = c1; pg = sx; po = sy; row = R0 + g; }
            else    { pi = sx; pf = sy; pg = c2; po = c3; row = R0 + g + 8; }
            int u = (V0 >> 2) + (tig >> 1);
            float4 xv = *(const float4*)(xg + (size_t)row * G4 + u * 4);
            float ci = Cin[(size_t)row * 1024 + u];
            float cn = sigf(pf + xv.y) * ci + sigf(pi + xv.x) * tanhf(pg + xv.z);
            float hv = sigf(po + xv.w) * tanhf(cn);
            Cout[(size_t)row * 1024 + u] = cn;
            hsm[(row - m0) * 32 + inv_l(u & 31)] = __float2half_rn(hv);
        }
    }
    __syncthreads();
    // coalesced permuted-h store: 128 rows x 64B
    {
        int r = tid >> 1, seg = tid & 1;
        int m = m0 + r;
        const uint4* src = (const uint4*)(hsm + r * 32 + seg * 16);
        uint4 a = src[0], b = src[1];
        __half* gd = Hout + (size_t)m * 1024 + (n0 >> 2) + seg * 16;
        *(uint4*)gd = a; *(uint4*)(gd + 8) = b;
        if ((m >> 8) == final_t) {
            __half* fd = Hfin + (size_t)m * 1024 + (n0 >> 2) + seg * 16;
            *(uint4*)fd = a; *(uint4*)(fd + 8) = b;
        }
    }
}

// ---------------- tensor-core linear ----------------
// MODE 1: projection -> fp32 gate-interleaved output, bias b0[wr]+b1[wr]
// MODE 0: classifier -> fp32 rows permuted (b*S+s), N-edge, bias b0[n]
template <int MODE>
__global__ void __launch_bounds__(256) k_mma_lin(
    const __half* __restrict__ A, const __half* __restrict__ W,
    float* __restrict__ Out, const float* __restrict__ b0,
    const float* __restrict__ b1, int N)
{
    extern __shared__ __half sm[];
    float* biasS = (float*)(sm + HTILE_OFF);
    const int tid = threadIdx.x, lane = tid & 31, wid = tid >> 5;
    const int wm = wid & 1, wn = wid >> 1, g = lane >> 2, tig = lane & 3;
    const int m0 = blockIdx.y * 128, n0 = blockIdx.x * 128;

    if (tid < 128) {
        int np = n0 + tid;
        float bv = 0.f;
        if (MODE == 1) { int wr = ((np & 3) << 10) | (np >> 2); bv = b0[wr] + b1[wr]; }
        else if (np < N) bv = b0[np];
        biasS[tid] = bv;
    }

    float acc[4][4][4];
#pragma unroll
    for (int a = 0; a < 4; a++)
#pragma unroll
        for (int b = 0; b < 4; b++)
#pragma unroll
            for (int c = 0; c < 4; c++) acc[a][b][c] = 0.f;

    run_mainloop<(MODE == 0) ? 1 : 0>(sm, A, W, m0, n0, MODE ? 0x7fffffff : N,
                                      acc, tid, wm, wn, g, tig);

#pragma unroll
    for (int mi = 0; mi < 4; mi++) {
        const int R0 = m0 + wm * 64 + mi * 16;
#pragma unroll
        for (int ni = 0; ni < 4; ni++) {
            const int V0 = n0 + wn * 32 + ni * 8;
            const int v = V0 + 2 * tig;
            const float bA0 = biasS[v - n0], bA1 = biasS[v - n0 + 1];
            const int r1 = R0 + g, r2 = R0 + g + 8;
            if (MODE == 1) {
                float2 s1 = make_float2(acc[mi][ni][0] + bA0, acc[mi][ni][1] + bA1);
                float2 s2 = make_float2(acc[mi][ni][2] + bA0, acc[mi][ni][3] + bA1);
                *(float2*)(Out + (size_t)r1 * G4 + v) = s1;
                *(float2*)(Out + (size_t)r2 * G4 + v) = s2;
            } else {
                int or1 = (r1 & 255) * S_ + (r1 >> 8);
                int or2 = (r2 & 255) * S_ + (r2 >> 8);
                if (v < N) {
                    Out[(size_t)or1 * N + v] = acc[mi][ni][0] + bA0;
                    Out[(size_t)or2 * N + v] = acc[mi][ni][2] + bA0;
                }
                if (v + 1 < N) {
                    Out[(size_t)or1 * N + v + 1] = acc[mi][ni][1] + bA1;
                    Out[(size_t)or2 * N + v + 1] = acc[mi][ni][3] + bA1;
                }
            }
        }
    }
}

// ---------------- prep kernels (fp32 -> fp16 + k-permute) ----------------
// one thread = one 32-half output block
template <int REMAP>
__global__ void k_prep_w(const float* __restrict__ in, __half* __restrict__ out, int rows) {
    int idx = blockIdx.x * blockDim.x + threadIdx.x;
    if (idx >= rows * 32) return;
    int r = idx >> 5, b32 = idx & 31;
    int wr = REMAP ? (((r & 3) << 10) | (r >> 2)) : r;
    const float* src = in + (size_t)wr * 1024 + b32 * 32;
    float v[32];
#pragma unroll
    for (int i = 0; i < 8; i++) *(float4*)&v[i * 4] = *(const float4*)(src + i * 4);
    __half h[32];
#pragma unroll
    for (int p = 0; p < 32; p++) h[p] = __float2half_rn(v[perm_l(p)]);
    uint4* dst = (uint4*)(out + (size_t)r * 1024 + b32 * 32);
#pragma unroll
    for (int i = 0; i < 4; i++) dst[i] = ((const uint4*)h)[i];
}

// transpose [B,S,F]->[S,B,F] + fp16 + permute
__global__ void k_xTh(const float* __restrict__ in, __half* __restrict__ out) {
    int idx = blockIdx.x * blockDim.x + threadIdx.x;
    if (idx >= SB * 32) return;
    int r = idx >> 5, b32 = idx & 31;
    int b = r % B_, s = r / B_;
    const float* src = in + (size_t)(b * S_ + s) * 1024 + b32 * 32;
    float v[32];
#pragma unroll
    for (int i = 0; i < 8; i++) *(float4*)&v[i * 4] = *(const float4*)(src + i * 4);
    __half h[32];
#pragma unroll
    for (int p = 0; p < 32; p++) h[p] = __float2half_rn(v[perm_l(p)]);
    uint4* dst = (uint4*)(out + (size_t)r * 1024 + b32 * 32);
#pragma unroll
    for (int i = 0; i < 4; i++) dst[i] = ((const uint4*)h)[i];
}

// hs (fp32 logical) -> hu0 (fp16 permuted)
__global__ void k_h2h(const float* __restrict__ in, __half* __restrict__ out) {
    int idx = blockIdx.x * blockDim.x + threadIdx.x;
    if (idx >= SB * 32) return;
    int r = idx >> 5, b32 = idx & 31;
    const float* src = in + (size_t)r * 1024 + b32 * 32;
    float v[32];
#pragma unroll
    for (int i = 0; i < 8; i++) *(float4*)&v[i * 4] = *(const float4*)(src + i * 4);
    __half h[32];
#pragma unroll
    for (int p = 0; p < 32; p++) h[p] = __float2half_rn(v[perm_l(p)]);
    uint4* dst = (uint4*)(out + (size_t)r * 1024 + b32 * 32);
#pragma unroll
    for (int i = 0; i < 4; i++) dst[i] = ((const uint4*)h)[i];
}

// ---------------- FFMA rolling LSTM step (fp32-exact, M=256) ----------------
__global__ void __launch_bounds__(256) k_lstm_step(
    const float* __restrict__ Hin, const float* __restrict__ Whh,
    const float* __restrict__ xg, const float* __restrict__ Cin,
    float* __restrict__ Hout, float* __restrict__ Cout, int zeroInit)
{
    constexpr int BM = 64, TM = 4;
    __shared__ float As[16][BM + 4];
    __shared__ float Ws[16][132];
    const int tid = threadIdx.x;
    const int tx = tid & 15, ty = tid >> 4;
    const int m0 = blockIdx.y * BM;
    const int n0 = blockIdx.x * 128;

    float acc[TM][8];
#pragma unroll
    for (int i = 0; i < TM; i++)
#pragma unroll
        for (int j = 0; j < 8; j++) acc[i][j] = 0.f;

    if (!zeroInit) {
        const int lr = tid >> 2;
        const int lk = (tid & 3) << 2;
        for (int kt = 0; kt < 1024; kt += 16) {
            {
                int row = lr;
                float4 v = *(const float4*)&Hin[(size_t)(m0 + row) * 1024 + kt + lk];
                As[lk + 0][row] = v.x; As[lk + 1][row] = v.y;
                As[lk + 2][row] = v.z; As[lk + 3][row] = v.w;
            }
#pragma unroll
            for (int r = 0; r < 2; r++) {
                int wr = lr + r * 64;
                int np = n0 + wr;
                int wrow = ((np & 3) << 10) + (np >> 2);
                float4 v = *(const float4*)&Whh[(size_t)wrow * 1024 + kt + lk];
                Ws[lk + 0][wr] = v.x; Ws[lk + 1][wr] = v.y;
                Ws[lk + 2][wr] = v.z; Ws[lk + 3][wr] = v.w;
            }
            __syncthreads();
#pragma unroll
            for (int k = 0; k < 16; k++) {
                float a[TM], w[8];
#pragma unroll
                for (int i = 0; i < TM; i++) a[i] = As[k][ty * TM + i];
#pragma unroll
                for (int j = 0; j < 8; j++) w[j] = Ws[k][tx * 8 + j];
#pragma unroll
                for (int i = 0; i < TM; i++)
#pragma unroll
                    for (int j = 0; j < 8; j++) acc[i][j] = fmaf(a[i], w[j], acc[i][j]);
            }
            __syncthreads();
        }
    }

    const int u0 = (n0 + tx * 8) >> 2;
#pragma unroll
    for (int i = 0; i < TM; i++) {
        int m = m0 + ty * TM + i;
        const float* xr = xg + (size_t)m * G4;
#pragma unroll
        for (int uu = 0; uu < 2; uu++) {
            int u = u0 + uu;
            float4 xv = *(const float4*)&xr[(size_t)u * 4];
            float pi = acc[i][uu * 4 + 0] + xv.x;
            float pf = acc[i][uu * 4 + 1] + xv.y;
            float pg = acc[i][uu * 4 + 2] + xv.z;
            float po = acc[i][uu * 4 + 3] + xv.w;
            float c  = zeroInit ? 0.f : Cin[(size_t)m * 1024 + u];
            float c2 = sigf(pf) * c + sigf(pi) * tanhf(pg);
            float h2 = sigf(po) * tanhf(c2);
            Hout[(size_t)m * 1024 + u] = h2;
            Cout[(size_t)m * 1024 + u] = c2;
        }
    }
}

// ---------------- host orchestration ----------------
extern "C" void kernel_launch(void* const* d_in, const int* in_sizes, int n_in,
                              void* d_out, int out_size) {
    (void)in_sizes; (void)n_in; (void)out_size;
    const float* inp   = (const float*)d_in[0];
    const float* Wih_r = (const float*)d_in[1];
    const float* Whh_r = (const float*)d_in[2];
    const float* bih_r = (const float*)d_in[3];
    const float* bhh_r = (const float*)d_in[4];
    const float* Wih_u = (const float*)d_in[5];
    const float* Whh_u = (const float*)d_in[6];
    const float* bih_u = (const float*)d_in[7];
    const float* bhh_u = (const float*)d_in[8];
    const float* Wc    = (const float*)d_in[9];
    const float* bc    = (const float*)d_in[10];
    float* out = (float*)d_out;

    __half *xT, *hu, *hn, *wihr, *wihu, *whhu, *wc;
    float *xg_r, *xg_u, *hs, *cs, *cu;
    cudaGetSymbolAddress((void**)&xT,   g_xT);
    cudaGetSymbolAddress((void**)&xg_r, g_xg_r);
    cudaGetSymbolAddress((void**)&xg_u, g_xg_u);
    cudaGetSymbolAddress((void**)&hs,   g_hs);
    cudaGetSymbolAddress((void**)&cs,   g_cs);
    cudaGetSymbolAddress((void**)&hu,   g_hu);
    cudaGetSymbolAddress((void**)&cu,   g_cu);
    cudaGetSymbolAddress((void**)&hn,   g_hn);
    cudaGetSymbolAddress((void**)&wihr, g_wihr);
    cudaGetSymbolAddress((void**)&wihu, g_wihu);
    cudaGetSymbolAddress((void**)&whhu, g_whhu);
    cudaGetSymbolAddress((void**)&wc,   g_wc);
    __half* hu0 = hu;
    __half* hu1 = hu + (size_t)SB * 1024;

    cudaFuncSetAttribute(k_mma_lstm,   cudaFuncAttributeMaxDynamicSharedMemorySize, SMEM_LSTM);
    cudaFuncSetAttribute(k_mma_lin<1>, cudaFuncAttributeMaxDynamicSharedMemorySize, SMEM_LIN);
    cudaFuncSetAttribute(k_mma_lin<0>, cudaFuncAttributeMaxDynamicSharedMemorySize, SMEM_LIN);

    // 0) prep: convert + permute all GEMM operands to fp16
    k_xTh<<<(SB * 32 + 255) / 256, 256>>>(inp, xT);
    k_prep_w<1><<<(G4 * 32 + 255) / 256, 256>>>(Wih_r, wihr, G4);
    k_prep_w<1><<<(G4 * 32 + 255) / 256, 256>>>(Wih_u, wihu, G4);
    k_prep_w<1><<<(G4 * 32 + 255) / 256, 256>>>(Whh_u, whhu, G4);
    k_prep_w<0><<<(C_ * 32 + 255) / 256, 256>>>(Wc, wc, C_);

    // 1) input projections -> gate-interleaved fp32 xg
    {
        dim3 g(G4 / 128, SB / 128);
        k_mma_lin<1><<<g, 256, SMEM_LIN>>>(xT, wihr, xg_r, bih_r, bhh_r, G4);
        k_mma_lin<1><<<g, 256, SMEM_LIN>>>(xT, wihu, xg_u, bih_u, bhh_u, G4);
    }

    // 2) rolling LSTM: 14 sequential FFMA steps (fp32-exact)
    for (int t = 0; t < S_; t++) {
        dim3 g(G4 / 128, B_ / 64);
        const float* hin = (t == 0) ? nullptr : hs + (size_t)(t - 1) * BH;
        const float* cin = (t == 0) ? nullptr : cs + (size_t)(t - 1) * BH;
        k_lstm_step<<<g, 256>>>(hin, Whh_r,
                                xg_r + (size_t)t * B_ * G4, cin,
                                hs + (size_t)t * BH, cs + (size_t)t * BH,
                                (t == 0) ? 1 : 0);
    }

    // 3) init unroll state (h -> fp16 permuted; c exact fp32)
    k_h2h<<<(SB * 32 + 255) / 256, 256>>>(hs, hu0);
    cudaMemcpyAsync(cu, cs, sizeof(float) * (size_t)SB * 1024, cudaMemcpyDeviceToDevice, 0);

    // 4) unrolling LSTM: 15 batched fp16 tensor-core steps over the active prefix
    for (int j = 0; j <= S_; j++) {
        int nact = (15 - j < 14) ? (15 - j) : 14;
        const __half* hin = (j & 1) ? hu1 : hu0;
        __half*       ho  = (j & 1) ? hu0 : hu1;
        int final_t = S_ - j;
        dim3 g(G4 / 128, nact * 2);
        k_mma_lstm<<<g, 256, SMEM_LSTM>>>(hin, whhu, xg_u, cu, ho, cu, hn, final_t);
    }

    // 5) classifier (rows permuted to [B,S], N-edge)
    {
        dim3 g((C_ + 127) / 128, SB / 128);
        k_mma_lin<0><<<g, 256, SMEM_LIN>>>(hn, wc, out, bc, nullptr, C_);
    }
}